// round 9
// baseline (speedup 1.0000x reference)
#include <cuda_runtime.h>

// LUT-tree conv: B=8, C=64, H=W=32, O=32, Q=8, K=3.
// R7: single-wave residency (launch_bounds 128x8 -> all 1024 blocks in 1 wave),
//     constant-folded Möbius tables for the three 0.5-padded LUTs
//     (level1#4 -> 4 coeffs, level2#1 -> 2 coeffs, level3 -> 4 coeffs),
//     scalar Möbius-Horner elsewhere (15 FMA, no FADD).

#define STRIDE 36
#define HROWS  10                    // 8 output rows + 2 halo
#define PLANE  (HROWS * STRIDE)      // 360 floats per channel plane

__device__ __forceinline__ float fsig(float x) {
    // sigmoid via ex2.approx + rcp.approx (~1e-6 rel err, 2 MUFU)
    float e, r;
    asm("ex2.approx.f32 %0, %1;" : "=f"(e) : "f"(x * -1.4426950408889634f));
    asm("rcp.approx.f32 %0, %1;" : "=f"(r) : "f"(1.0f + e));
    return r;
}

// Horner eval of multilinear interp with Möbius coeffs: 15 FMA, zero FADD.
__device__ __forceinline__ float lut4m(const float c[16],
                                       float x0, float x1, float x2, float x3) {
    float u0 = fmaf(x0, c[1],  c[0]);
    float u1 = fmaf(x0, c[3],  c[2]);
    float u2 = fmaf(x0, c[5],  c[4]);
    float u3 = fmaf(x0, c[7],  c[6]);
    float u4 = fmaf(x0, c[9],  c[8]);
    float u5 = fmaf(x0, c[11], c[10]);
    float u6 = fmaf(x0, c[13], c[12]);
    float u7 = fmaf(x0, c[15], c[14]);
    float v0 = fmaf(x1, u1, u0);
    float v1 = fmaf(x1, u3, u2);
    float v2 = fmaf(x1, u5, u4);
    float v3 = fmaf(x1, u7, u6);
    float w0 = fmaf(x2, v1, v0);
    float w1 = fmaf(x2, v3, v2);
    return fmaf(x3, w1, w0);
}

// 2-input folded LUT: 3 FMA.
__device__ __forceinline__ float lut2m(float4 c, float x0, float x1) {
    return fmaf(x1, fmaf(x0, c.w, c.z), fmaf(x0, c.y, c.x));
}

// Coeff fetch: 4x LDS.128 broadcast (uniform address).
__device__ __forceinline__ void ldc16(float c[16], const float* Wc, int lut) {
    const float4* p = reinterpret_cast<const float4*>(Wc + lut * 16);
    #pragma unroll
    for (int j = 0; j < 4; j++) {
        float4 t = p[j];
        c[4*j+0] = t.x; c[4*j+1] = t.y; c[4*j+2] = t.z; c[4*j+3] = t.w;
    }
}

__global__ __launch_bounds__(128, 8) void lut_tree_kernel(
    const float* __restrict__ x,
    const float* __restrict__ w0, const float* __restrict__ w1,
    const float* __restrict__ w2, const float* __restrict__ w3,
    const int* __restrict__ ci, float* __restrict__ out)
{
    __shared__ __align__(16) float S[8 * PLANE];   // sigmoided channels + halo
    __shared__ __align__(16) float Wc[26 * 16];    // Möbius coeffs (some folded)

    const int o   = blockIdx.x;          // 0..31
    const int b   = blockIdx.y;          // 0..7
    const int h0  = blockIdx.z << 3;     // 0,8,16,24
    const int tid = threadIdx.x;

    // ---- Stage + Möbius-transform (+constant-fold) weights; thread t = LUT t ----
    if (tid < 26) {
        const float* src;
        if (tid < 18)      src = w0 + o * 288 + tid * 16;
        else if (tid < 23) src = w1 + o * 80  + (tid - 18) * 16;
        else if (tid < 25) src = w2 + o * 32  + (tid - 23) * 16;
        else               src = w3 + o * 16;
        float t16[16];
        #pragma unroll
        for (int i = 0; i < 16; i++) t16[i] = src[i];
        // finite-difference (Möbius) transform along each dim
        #pragma unroll
        for (int d = 0; d < 4; d++) {
            const int s = 1 << d;
            #pragma unroll
            for (int j = 0; j < 16; j++)
                if (j & s) t16[j] -= t16[j ^ s];
        }
        // fold constant-0.5 inputs: LUT22 (lvl1#4) & LUT25 (lvl3) fold dims 3,2;
        // LUT24 (lvl2#1) folds dims 3,2,1.  c'_S = c_S + 0.5*c_{S|bit}.
        const int nfold = (tid == 22 || tid == 25) ? 2 : (tid == 24 ? 3 : 0);
        for (int d = 3; d > 3 - nfold; d--) {
            const int s = 1 << d;
            for (int j = 0; j < s; j++) t16[j] += 0.5f * t16[j + s];
        }
        #pragma unroll
        for (int i = 0; i < 16; i++) Wc[tid * 16 + i] = t16[i];
    }

    // ---- Init planes to sigmoid(0)=0.5 (covers conv zero-pad halo) ----
    {
        float4 hv = make_float4(0.5f, 0.5f, 0.5f, 0.5f);
        float4* S4 = reinterpret_cast<float4*>(S);
        for (int i = tid; i < 8 * PLANE / 4; i += 128) S4[i] = hv;
    }
    __syncthreads();

    // ---- Fill interior: sigmoid of selected channels for this h-quarter ----
    #pragma unroll
    for (int q = 0; q < 8; q++) {
        const int ch = ci[o * 8 + q];
        const float* xc = x + ((size_t)(b * 64 + ch)) * 1024;
        for (int i = tid; i < HROWS * 32; i += 128) {
            const int r = i >> 5, w = i & 31;
            const int hin = h0 - 1 + r;
            if (hin >= 0 && hin < 32)
                S[q * PLANE + r * STRIDE + 1 + w] = fsig(xc[hin * 32 + w]);
        }
    }
    __syncthreads();

    // ---- Eval: thread -> output row ty (of 8), 2 consecutive cols ----
    const int ty = tid >> 4;              // 0..7
    const int wb = (tid & 15) << 1;       // 0..30 (8B aligned)

    float h1s[2][5];   // sigmoided level-1 outputs per pixel

    #pragma unroll
    for (int g = 0; g < 5; g++) {
        const int nk = (g < 4) ? 4 : 2;   // g=4: inputs 2,3 folded away
        float in[4][2];
        #pragma unroll
        for (int k = 0; k < 4; k++) {
            if (k >= nk) continue;
            const int l = g * 4 + k;      // < 18 always for evaluated k
            float c[16]; ldc16(c, Wc, l);
            // features j=4l..4l+3 span exactly 2 feature-rows rA, rA+1
            const int rA = (4 * l) / 3;
            const int rB = rA + 1;
            float va[4], vb[4];
            {
                const float* pa = S + (rA / 3) * PLANE + (ty + rA % 3) * STRIDE + wb;
                float2 f0 = *(const float2*)pa;
                float2 f1 = *(const float2*)(pa + 2);
                va[0] = f0.x; va[1] = f0.y; va[2] = f1.x; va[3] = f1.y;
            }
            {
                const float* pb = S + (rB / 3) * PLANE + (ty + rB % 3) * STRIDE + wb;
                float2 f0 = *(const float2*)pb;
                float2 f1 = *(const float2*)(pb + 2);
                vb[0] = f0.x; vb[1] = f0.y; vb[2] = f1.x; vb[3] = f1.y;
            }
            #pragma unroll
            for (int p = 0; p < 2; p++) {
                float xi[4];
                #pragma unroll
                for (int i = 0; i < 4; i++) {
                    const int j  = 4 * l + i;        // compile-time
                    const int rr = j / 3;
                    const int kw = j % 3;
                    xi[i] = (rr == rA) ? va[kw + p] : vb[kw + p];
                }
                in[k][p] = fsig(lut4m(c, xi[0], xi[1], xi[2], xi[3]));
            }
        }
        if (g < 4) {
            float c[16]; ldc16(c, Wc, 18 + g);
            #pragma unroll
            for (int p = 0; p < 2; p++)
                h1s[p][g] = fsig(lut4m(c, in[0][p], in[1][p], in[2][p], in[3][p]));
        } else {
            float4 c4 = *reinterpret_cast<const float4*>(Wc + 22 * 16);
            #pragma unroll
            for (int p = 0; p < 2; p++)
                h1s[p][4] = fsig(lut2m(c4, in[0][p], in[1][p]));
        }
    }

    // Level 2: LUT23 full; LUT24 folded to linear (1 FMA).
    float h2s[2][2];
    {
        float c[16]; ldc16(c, Wc, 23);
        #pragma unroll
        for (int p = 0; p < 2; p++)
            h2s[p][0] = fsig(lut4m(c, h1s[p][0], h1s[p][1], h1s[p][2], h1s[p][3]));
    }
    {
        float2 c2 = *reinterpret_cast<const float2*>(Wc + 24 * 16);
        #pragma unroll
        for (int p = 0; p < 2; p++)
            h2s[p][1] = fsig(fmaf(h1s[p][4], c2.y, c2.x));
    }

    // Level 3 (no sigmoid): folded bilinear (3 FMA).
    float2 ov;
    {
        float4 c4 = *reinterpret_cast<const float4*>(Wc + 25 * 16);
        ov.x = lut2m(c4, h2s[0][0], h2s[0][1]);
        ov.y = lut2m(c4, h2s[1][0], h2s[1][1]);
    }

    const int h = h0 + ty;
    *reinterpret_cast<float2*>(&out[(((b * 32 + o) * 32 + h) * 32) + wb]) = ov;
}

extern "C" void kernel_launch(void* const* d_in, const int* in_sizes, int n_in,
                              void* d_out, int out_size) {
    const float* x  = (const float*)d_in[0];
    const float* w0 = (const float*)d_in[1];
    const float* w1 = (const float*)d_in[2];
    const float* w2 = (const float*)d_in[3];
    const float* w3 = (const float*)d_in[4];
    const int*   ci = (const int*)d_in[5];
    dim3 grid(32, 8, 4);   // (O, B, H-quarter)
    lut_tree_kernel<<<grid, 128>>>(x, w0, w1, w2, w3, ci, (float*)d_out);
}

// round 10
// speedup vs baseline: 1.4839x; 1.4839x over previous
#include <cuda_runtime.h>

// LUT-tree conv: B=8, C=64, H=W=32, O=32, Q=8, K=3.
// R8: R6 structure + validated Möbius constant-folding,
//     launch_bounds(128,7) -> 7 blocks/SM, single wave, regs fit (no R7 spills),
//     pre-pass sigmoid kernel into __device__ g_sig (kills fill MUFU + redundancy),
//     rolling feature-row (va/vb) reuse across level-0 LUTs (48 vs 72 LDS.64).

#define STRIDE 36
#define HROWS  10                    // 8 output rows + 2 halo
#define PLANE  (HROWS * STRIDE)      // 360 floats per channel plane

__device__ float g_sig[8 * 64 * 32 * 32];   // sigmoid(x), written by pre-pass

__device__ __forceinline__ float fsig(float x) {
    float e, r;
    asm("ex2.approx.f32 %0, %1;" : "=f"(e) : "f"(x * -1.4426950408889634f));
    asm("rcp.approx.f32 %0, %1;" : "=f"(r) : "f"(1.0f + e));
    return r;
}

// Horner eval of multilinear interp with Möbius coeffs: 15 FMA, zero FADD.
__device__ __forceinline__ float lut4m(const float c[16],
                                       float x0, float x1, float x2, float x3) {
    float u0 = fmaf(x0, c[1],  c[0]);
    float u1 = fmaf(x0, c[3],  c[2]);
    float u2 = fmaf(x0, c[5],  c[4]);
    float u3 = fmaf(x0, c[7],  c[6]);
    float u4 = fmaf(x0, c[9],  c[8]);
    float u5 = fmaf(x0, c[11], c[10]);
    float u6 = fmaf(x0, c[13], c[12]);
    float u7 = fmaf(x0, c[15], c[14]);
    float v0 = fmaf(x1, u1, u0);
    float v1 = fmaf(x1, u3, u2);
    float v2 = fmaf(x1, u5, u4);
    float v3 = fmaf(x1, u7, u6);
    float w0 = fmaf(x2, v1, v0);
    float w1 = fmaf(x2, v3, v2);
    return fmaf(x3, w1, w0);
}

// 2-input folded LUT: 3 FMA.
__device__ __forceinline__ float lut2m(float4 c, float x0, float x1) {
    return fmaf(x1, fmaf(x0, c.w, c.z), fmaf(x0, c.y, c.x));
}

// Coeff fetch: 4x LDS.128 broadcast (uniform address).
__device__ __forceinline__ void ldc16(float c[16], const float* Wc, int lut) {
    const float4* p = reinterpret_cast<const float4*>(Wc + lut * 16);
    #pragma unroll
    for (int j = 0; j < 4; j++) {
        float4 t = p[j];
        c[4*j+0] = t.x; c[4*j+1] = t.y; c[4*j+2] = t.z; c[4*j+3] = t.w;
    }
}

// ---- Pre-pass: sigmoid the whole input once ----
__global__ __launch_bounds__(256) void sig_prepass(const float* __restrict__ x) {
    const int i = blockIdx.x * 256 + threadIdx.x;   // 131072 float4 total
    float4 v = reinterpret_cast<const float4*>(x)[i];
    v.x = fsig(v.x); v.y = fsig(v.y); v.z = fsig(v.z); v.w = fsig(v.w);
    reinterpret_cast<float4*>(g_sig)[i] = v;
}

__global__ __launch_bounds__(128, 7) void lut_tree_kernel(
    const float* __restrict__ w0, const float* __restrict__ w1,
    const float* __restrict__ w2, const float* __restrict__ w3,
    const int* __restrict__ ci, float* __restrict__ out)
{
    __shared__ __align__(16) float S[8 * PLANE];   // sigmoided channels + halo
    __shared__ __align__(16) float Wc[26 * 16];    // Möbius coeffs (some folded)

    const int o   = blockIdx.x;          // 0..31
    const int b   = blockIdx.y;          // 0..7
    const int h0  = blockIdx.z << 3;     // 0,8,16,24
    const int tid = threadIdx.x;

    // ---- Stage + Möbius-transform (+constant-fold) weights; thread t = LUT t ----
    if (tid < 26) {
        const float* src;
        if (tid < 18)      src = w0 + o * 288 + tid * 16;
        else if (tid < 23) src = w1 + o * 80  + (tid - 18) * 16;
        else if (tid < 25) src = w2 + o * 32  + (tid - 23) * 16;
        else               src = w3 + o * 16;
        float t16[16];
        #pragma unroll
        for (int i = 0; i < 16; i++) t16[i] = src[i];
        #pragma unroll
        for (int d = 0; d < 4; d++) {            // finite-difference transform
            const int s = 1 << d;
            #pragma unroll
            for (int j = 0; j < 16; j++)
                if (j & s) t16[j] -= t16[j ^ s];
        }
        // fold constant-0.5 inputs: LUT22 & LUT25 fold dims 3,2; LUT24 dims 3,2,1.
        const int nfold = (tid == 22 || tid == 25) ? 2 : (tid == 24 ? 3 : 0);
        for (int d = 3; d > 3 - nfold; d--) {
            const int s = 1 << d;
            for (int j = 0; j < s; j++) t16[j] += 0.5f * t16[j + s];
        }
        #pragma unroll
        for (int i = 0; i < 16; i++) Wc[tid * 16 + i] = t16[i];
    }

    // ---- Init planes to 0.5 (covers conv zero-pad halo) ----
    {
        float4 hv = make_float4(0.5f, 0.5f, 0.5f, 0.5f);
        float4* S4 = reinterpret_cast<float4*>(S);
        for (int i = tid; i < 8 * PLANE / 4; i += 128) S4[i] = hv;
    }
    __syncthreads();

    // ---- Fill interior from pre-sigmoided g_sig (pure copy, no MUFU) ----
    #pragma unroll
    for (int q = 0; q < 8; q++) {
        const int ch = ci[o * 8 + q];
        const float* xc = g_sig + ((size_t)(b * 64 + ch)) * 1024;
        #pragma unroll
        for (int i0 = 0; i0 < HROWS * 32; i0 += 128) {
            const int i = i0 + tid;
            if (i < HROWS * 32) {
                const int r = i >> 5, w = i & 31;
                const int hin = h0 - 1 + r;
                if (hin >= 0 && hin < 32)
                    S[q * PLANE + r * STRIDE + 1 + w] = xc[hin * 32 + w];
            }
        }
    }
    __syncthreads();

    // ---- Eval: thread -> output row ty (of 8), 2 consecutive cols ----
    const int ty = tid >> 4;              // 0..7
    const int wb = (tid & 15) << 1;       // 0..30 (8B aligned)

    // Rolling feature-row pair: va = row rA, vb = row rA+1 (rA = 4l/3).
    float va[4], vb[4];
    #define LOADROW(dst, R) do {                                               \
        const float* p_ = S + ((R) / 3) * PLANE + (ty + (R) % 3) * STRIDE + wb;\
        float2 f0_ = *(const float2*)p_;                                       \
        float2 f1_ = *(const float2*)(p_ + 2);                                 \
        dst[0] = f0_.x; dst[1] = f0_.y; dst[2] = f1_.x; dst[3] = f1_.y;        \
    } while (0)

    float ing[4][2];   // current level-1 group inputs
    float h1s[2][5];   // sigmoided level-1 outputs per pixel

    LOADROW(va, 0);
    LOADROW(vb, 1);

    #pragma unroll
    for (int l = 0; l < 18; l++) {
        const int k = l & 3;
        const int g = l >> 2;
        const int rA = (4 * l) / 3;
        float c[16]; ldc16(c, Wc, l);
        #pragma unroll
        for (int p = 0; p < 2; p++) {
            float xi[4];
            #pragma unroll
            for (int i = 0; i < 4; i++) {
                const int j  = 4 * l + i;     // compile-time
                const int rr = j / 3;
                const int kw = j % 3;
                xi[i] = (rr == rA) ? va[kw + p] : vb[kw + p];
            }
            ing[k][p] = fsig(lut4m(c, xi[0], xi[1], xi[2], xi[3]));
        }
        // level-1 reduction when a group completes
        if (k == 3) {                        // groups 0..3 (full LUT4)
            float cg[16]; ldc16(cg, Wc, 18 + g);
            #pragma unroll
            for (int p = 0; p < 2; p++)
                h1s[p][g] = fsig(lut4m(cg, ing[0][p], ing[1][p], ing[2][p], ing[3][p]));
        }
        if (l == 17) {                       // group 4: folded 2-input LUT
            float4 c4 = *reinterpret_cast<const float4*>(Wc + 22 * 16);
            #pragma unroll
            for (int p = 0; p < 2; p++)
                h1s[p][4] = fsig(lut2m(c4, ing[0][p], ing[1][p]));
        }
        // advance rolling rows
        if (l < 17) {
            const int rN = (4 * (l + 1)) / 3;
            if (rN == rA + 1) {
                #pragma unroll
                for (int i = 0; i < 4; i++) va[i] = vb[i];
                LOADROW(vb, rN + 1);
            } else {
                LOADROW(va, rN);
                LOADROW(vb, rN + 1);
            }
        }
    }
    #undef LOADROW

    // Level 2: LUT23 full; LUT24 folded to linear (1 FMA).
    float h2s[2][2];
    {
        float c[16]; ldc16(c, Wc, 23);
        #pragma unroll
        for (int p = 0; p < 2; p++)
            h2s[p][0] = fsig(lut4m(c, h1s[p][0], h1s[p][1], h1s[p][2], h1s[p][3]));
    }
    {
        float2 c2 = *reinterpret_cast<const float2*>(Wc + 24 * 16);
        #pragma unroll
        for (int p = 0; p < 2; p++)
            h2s[p][1] = fsig(fmaf(h1s[p][4], c2.y, c2.x));
    }

    // Level 3 (no sigmoid): folded bilinear (3 FMA).
    float2 ov;
    {
        float4 c4 = *reinterpret_cast<const float4*>(Wc + 25 * 16);
        ov.x = lut2m(c4, h2s[0][0], h2s[0][1]);
        ov.y = lut2m(c4, h2s[1][0], h2s[1][1]);
    }

    const int h = h0 + ty;
    *reinterpret_cast<float2*>(&out[(((b * 32 + o) * 32 + h) * 32) + wb]) = ov;
}

extern "C" void kernel_launch(void* const* d_in, const int* in_sizes, int n_in,
                              void* d_out, int out_size) {
    const float* x  = (const float*)d_in[0];
    const float* w0 = (const float*)d_in[1];
    const float* w1 = (const float*)d_in[2];
    const float* w2 = (const float*)d_in[3];
    const float* w3 = (const float*)d_in[4];
    const int*   ci = (const int*)d_in[5];

    sig_prepass<<<512, 256>>>(x);                 // 131072 float4
    dim3 grid(32, 8, 4);                          // (O, B, H-quarter)
    lut_tree_kernel<<<grid, 128>>>(w0, w1, w2, w3, ci, (float*)d_out);
}

// round 12
// speedup vs baseline: 1.4896x; 1.0038x over previous
#include <cuda_runtime.h>

// LUT-tree conv: B=8, C=64, H=W=32, O=32, Q=8, K=3.
// R9: single fused kernel — prepass removed, sigmoid back in the fill loop
//     (reads x directly; eval core identical to the R8 winner:
//      Möbius-Horner + constant folding, rolling feature rows,
//      launch_bounds(128,7) single-wave residency).

#define STRIDE 36
#define HROWS  10                    // 8 output rows + 2 halo
#define PLANE  (HROWS * STRIDE)      // 360 floats per channel plane

__device__ __forceinline__ float fsig(float x) {
    float e, r;
    asm("ex2.approx.f32 %0, %1;" : "=f"(e) : "f"(x * -1.4426950408889634f));
    asm("rcp.approx.f32 %0, %1;" : "=f"(r) : "f"(1.0f + e));
    return r;
}

// Horner eval of multilinear interp with Möbius coeffs: 15 FMA, zero FADD.
__device__ __forceinline__ float lut4m(const float c[16],
                                       float x0, float x1, float x2, float x3) {
    float u0 = fmaf(x0, c[1],  c[0]);
    float u1 = fmaf(x0, c[3],  c[2]);
    float u2 = fmaf(x0, c[5],  c[4]);
    float u3 = fmaf(x0, c[7],  c[6]);
    float u4 = fmaf(x0, c[9],  c[8]);
    float u5 = fmaf(x0, c[11], c[10]);
    float u6 = fmaf(x0, c[13], c[12]);
    float u7 = fmaf(x0, c[15], c[14]);
    float v0 = fmaf(x1, u1, u0);
    float v1 = fmaf(x1, u3, u2);
    float v2 = fmaf(x1, u5, u4);
    float v3 = fmaf(x1, u7, u6);
    float w0 = fmaf(x2, v1, v0);
    float w1 = fmaf(x2, v3, v2);
    return fmaf(x3, w1, w0);
}

// 2-input folded LUT: 3 FMA.
__device__ __forceinline__ float lut2m(float4 c, float x0, float x1) {
    return fmaf(x1, fmaf(x0, c.w, c.z), fmaf(x0, c.y, c.x));
}

// Coeff fetch: 4x LDS.128 broadcast (uniform address).
__device__ __forceinline__ void ldc16(float c[16], const float* Wc, int lut) {
    const float4* p = reinterpret_cast<const float4*>(Wc + lut * 16);
    #pragma unroll
    for (int j = 0; j < 4; j++) {
        float4 t = p[j];
        c[4*j+0] = t.x; c[4*j+1] = t.y; c[4*j+2] = t.z; c[4*j+3] = t.w;
    }
}

__global__ __launch_bounds__(128, 7) void lut_tree_kernel(
    const float* __restrict__ x,
    const float* __restrict__ w0, const float* __restrict__ w1,
    const float* __restrict__ w2, const float* __restrict__ w3,
    const int* __restrict__ ci, float* __restrict__ out)
{
    __shared__ __align__(16) float S[8 * PLANE];   // sigmoided channels + halo
    __shared__ __align__(16) float Wc[26 * 16];    // Möbius coeffs (some folded)

    const int o   = blockIdx.x;          // 0..31
    const int b   = blockIdx.y;          // 0..7
    const int h0  = blockIdx.z << 3;     // 0,8,16,24
    const int tid = threadIdx.x;

    // ---- Stage + Möbius-transform (+constant-fold) weights; thread t = LUT t ----
    if (tid < 26) {
        const float* src;
        if (tid < 18)      src = w0 + o * 288 + tid * 16;
        else if (tid < 23) src = w1 + o * 80  + (tid - 18) * 16;
        else if (tid < 25) src = w2 + o * 32  + (tid - 23) * 16;
        else               src = w3 + o * 16;
        float t16[16];
        #pragma unroll
        for (int i = 0; i < 16; i++) t16[i] = src[i];
        #pragma unroll
        for (int d = 0; d < 4; d++) {            // finite-difference transform
            const int s = 1 << d;
            #pragma unroll
            for (int j = 0; j < 16; j++)
                if (j & s) t16[j] -= t16[j ^ s];
        }
        // fold constant-0.5 inputs: LUT22 & LUT25 fold dims 3,2; LUT24 dims 3,2,1.
        const int nfold = (tid == 22 || tid == 25) ? 2 : (tid == 24 ? 3 : 0);
        for (int d = 3; d > 3 - nfold; d--) {
            const int s = 1 << d;
            for (int j = 0; j < s; j++) t16[j] += 0.5f * t16[j + s];
        }
        #pragma unroll
        for (int i = 0; i < 16; i++) Wc[tid * 16 + i] = t16[i];
    }

    // ---- Init planes to 0.5 (covers conv zero-pad halo) ----
    {
        float4 hv = make_float4(0.5f, 0.5f, 0.5f, 0.5f);
        float4* S4 = reinterpret_cast<float4*>(S);
        for (int i = tid; i < 8 * PLANE / 4; i += 128) S4[i] = hv;
    }
    __syncthreads();

    // ---- Fill interior: sigmoid of selected channels for this h-quarter ----
    #pragma unroll
    for (int q = 0; q < 8; q++) {
        const int ch = ci[o * 8 + q];
        const float* xc = x + ((size_t)(b * 64 + ch)) * 1024;
        #pragma unroll
        for (int i0 = 0; i0 < HROWS * 32; i0 += 128) {
            const int i = i0 + tid;
            if (i < HROWS * 32) {
                const int r = i >> 5, w = i & 31;
                const int hin = h0 - 1 + r;
                if (hin >= 0 && hin < 32)
                    S[q * PLANE + r * STRIDE + 1 + w] = fsig(xc[hin * 32 + w]);
            }
        }
    }
    __syncthreads();

    // ---- Eval: thread -> output row ty (of 8), 2 consecutive cols ----
    const int ty = tid >> 4;              // 0..7
    const int wb = (tid & 15) << 1;       // 0..30 (8B aligned)

    // Rolling feature-row pair: va = row rA, vb = row rA+1 (rA = 4l/3).
    float va[4], vb[4];
    #define LOADROW(dst, R) do {                                               \
        const float* p_ = S + ((R) / 3) * PLANE + (ty + (R) % 3) * STRIDE + wb;\
        float2 f0_ = *(const float2*)p_;                                       \
        float2 f1_ = *(const float2*)(p_ + 2);                                 \
        dst[0] = f0_.x; dst[1] = f0_.y; dst[2] = f1_.x; dst[3] = f1_.y;        \
    } while (0)

    float ing[4][2];   // current level-1 group inputs
    float h1s[2][5];   // sigmoided level-1 outputs per pixel

    LOADROW(va, 0);
    LOADROW(vb, 1);

    #pragma unroll
    for (int l = 0; l < 18; l++) {
        const int k = l & 3;
        const int g = l >> 2;
        const int rA = (4 * l) / 3;
        float c[16]; ldc16(c, Wc, l);
        #pragma unroll
        for (int p = 0; p < 2; p++) {
            float xi[4];
            #pragma unroll
            for (int i = 0; i < 4; i++) {
                const int j  = 4 * l + i;     // compile-time
                const int rr = j / 3;
                const int kw = j % 3;
                xi[i] = (rr == rA) ? va[kw + p] : vb[kw + p];
            }
            ing[k][p] = fsig(lut4m(c, xi[0], xi[1], xi[2], xi[3]));
        }
        // level-1 reduction when a group completes
        if (k == 3) {                        // groups 0..3 (full LUT4)
            float cg[16]; ldc16(cg, Wc, 18 + g);
            #pragma unroll
            for (int p = 0; p < 2; p++)
                h1s[p][g] = fsig(lut4m(cg, ing[0][p], ing[1][p], ing[2][p], ing[3][p]));
        }
        if (l == 17) {                       // group 4: folded 2-input LUT
            float4 c4 = *reinterpret_cast<const float4*>(Wc + 22 * 16);
            #pragma unroll
            for (int p = 0; p < 2; p++)
                h1s[p][4] = fsig(lut2m(c4, ing[0][p], ing[1][p]));
        }
        // advance rolling rows
        if (l < 17) {
            const int rN = (4 * (l + 1)) / 3;
            if (rN == rA + 1) {
                #pragma unroll
                for (int i = 0; i < 4; i++) va[i] = vb[i];
                LOADROW(vb, rN + 1);
            } else {
                LOADROW(va, rN);
                LOADROW(vb, rN + 1);
            }
        }
    }
    #undef LOADROW

    // Level 2: LUT23 full; LUT24 folded to linear (1 FMA).
    float h2s[2][2];
    {
        float c[16]; ldc16(c, Wc, 23);
        #pragma unroll
        for (int p = 0; p < 2; p++)
            h2s[p][0] = fsig(lut4m(c, h1s[p][0], h1s[p][1], h1s[p][2], h1s[p][3]));
    }
    {
        float2 c2 = *reinterpret_cast<const float2*>(Wc + 24 * 16);
        #pragma unroll
        for (int p = 0; p < 2; p++)
            h2s[p][1] = fsig(fmaf(h1s[p][4], c2.y, c2.x));
    }

    // Level 3 (no sigmoid): folded bilinear (3 FMA).
    float2 ov;
    {
        float4 c4 = *reinterpret_cast<const float4*>(Wc + 25 * 16);
        ov.x = lut2m(c4, h2s[0][0], h2s[0][1]);
        ov.y = lut2m(c4, h2s[1][0], h2s[1][1]);
    }

    const int h = h0 + ty;
    *reinterpret_cast<float2*>(&out[(((b * 32 + o) * 32 + h) * 32) + wb]) = ov;
}

extern "C" void kernel_launch(void* const* d_in, const int* in_sizes, int n_in,
                              void* d_out, int out_size) {
    const float* x  = (const float*)d_in[0];
    const float* w0 = (const float*)d_in[1];
    const float* w1 = (const float*)d_in[2];
    const float* w2 = (const float*)d_in[3];
    const float* w3 = (const float*)d_in[4];
    const int*   ci = (const int*)d_in[5];

    dim3 grid(32, 8, 4);   // (O, B, H-quarter) — single kernel, single wave
    lut_tree_kernel<<<grid, 128>>>(x, w0, w1, w2, w3, ci, (float*)d_out);
}